// round 8
// baseline (speedup 1.0000x reference)
#include <cuda_runtime.h>
#include <cuda_bf16.h>
#include <cstdint>
#include <float.h>

// Problem constants
#define NROI   256
#define FH     100
#define FW     50
#define FHW    5000
#define POOL   7
#define KFC    50176               // 1024 * 49
#define NFC    1024
#define NCLS   21

// GEMM decomposition: CTA tile 128x128, K-chunk 64, split-K 9
#define SPLITK     9
#define CHUNK_BASE 87              // 784 / 9
#define CHUNK_REM  1               // 784 % 9   (9*87+1 = 784 = KFC/64)

// smem tile layout (bytes, each sub-tile is 128 rows x 128B, SW128-swizzled)
#define TBYTES   16384             // one sub-tile (128 x 64 bf16)
#define BUFBYTES (4 * TBYTES)      // Ah, Al, Bh, Bl = 65536
#define SMEM_DYN (1024 + 2 * BUFBYTES)   // 132096

// Scratch (no cudaMalloc allowed)
__device__ __nv_bfloat16 g_a_hi[(size_t)NROI * KFC];
__device__ __nv_bfloat16 g_a_lo[(size_t)NROI * KFC];
__device__ float g_partial[(size_t)SPLITK * NROI * NFC];
__device__ float g_r[(size_t)NROI * NFC];

// ---------------------------------------------------------------------------
// Portable PTX helpers (all sm_80+; no 'a'-feature instructions)
// ---------------------------------------------------------------------------
__device__ __forceinline__ uint32_t cvta_smem(const void* p) {
    uint32_t a;
    asm("{ .reg .u64 t; cvta.to.shared.u64 t, %1; cvt.u32.u64 %0, t; }"
        : "=r"(a) : "l"(p));
    return a;
}
__device__ __forceinline__ void cpasync16(uint32_t s, const void* g) {
    asm volatile("cp.async.cg.shared.global [%0], [%1], 16;" :: "r"(s), "l"(g));
}
__device__ __forceinline__ void cpasync_commit() {
    asm volatile("cp.async.commit_group;" ::: "memory");
}
__device__ __forceinline__ void cpasync_wait0() {
    asm volatile("cp.async.wait_group 0;" ::: "memory");
}
__device__ __forceinline__ void ldm_x4(uint32_t* r, uint32_t a) {
    asm volatile("ldmatrix.sync.aligned.m8n8.x4.shared.b16 {%0,%1,%2,%3}, [%4];"
                 : "=r"(r[0]), "=r"(r[1]), "=r"(r[2]), "=r"(r[3]) : "r"(a));
}
__device__ __forceinline__ void ldm_x2(uint32_t* r, uint32_t a) {
    asm volatile("ldmatrix.sync.aligned.m8n8.x2.shared.b16 {%0,%1}, [%2];"
                 : "=r"(r[0]), "=r"(r[1]) : "r"(a));
}
__device__ __forceinline__ void mma_bf16(float* c, const uint32_t* a, const uint32_t* b) {
    asm volatile("mma.sync.aligned.m16n8k16.row.col.f32.bf16.bf16.f32 "
                 "{%0,%1,%2,%3}, {%4,%5,%6,%7}, {%8,%9}, {%0,%1,%2,%3};"
                 : "+f"(c[0]), "+f"(c[1]), "+f"(c[2]), "+f"(c[3])
                 : "r"(a[0]), "r"(a[1]), "r"(a[2]), "r"(a[3]), "r"(b[0]), "r"(b[1]));
}

// pack 8 floats -> 8 bf16 (hi) + 8 bf16 (lo), 16B each
struct alignas(16) bf16x8 { __nv_bfloat162 v[4]; };
__device__ __forceinline__ void split8(const float* f, bf16x8& hi, bf16x8& lo) {
#pragma unroll
    for (int j = 0; j < 4; j++) {
        __nv_bfloat16 h0 = __float2bfloat16_rn(f[2 * j]);
        __nv_bfloat16 h1 = __float2bfloat16_rn(f[2 * j + 1]);
        __nv_bfloat16 l0 = __float2bfloat16_rn(f[2 * j]     - __bfloat162float(h0));
        __nv_bfloat16 l1 = __float2bfloat16_rn(f[2 * j + 1] - __bfloat162float(h1));
        hi.v[j] = __nv_bfloat162{h0, h1};
        lo.v[j] = __nv_bfloat162{l0, l1};
    }
}
// SW128 swizzle of a byte offset within a 128B-row tile (16B granularity)
__device__ __forceinline__ uint32_t sw128(uint32_t off) {
    return off ^ ((off >> 3) & 0x70);
}

// ---------------------------------------------------------------------------
// Kernel 1: ROI adaptive max-pool 7x7 -> split-bf16 A (hi/lo).
// rois = max(proposals,0) // 16 ; reference maps h<-x (H=100), w<-y (W=50).
// pooled idx = c*49 + ph*7 + pw.
// ---------------------------------------------------------------------------
__global__ __launch_bounds__(512) void roi_pool_kernel(const float* __restrict__ fm,
                                                       const int* __restrict__ prop) {
    int roi = blockIdx.x;
    int4 p = *(const int4*)(prop + roi * 4);
    int h0 = max(p.x, 0) >> 4;
    int w0 = max(p.y, 0) >> 4;
    int h1 = max(p.z, 0) >> 4;
    int w1 = max(p.w, 0) >> 4;
    int sh = h1 - h0 + 1;
    int sw = w1 - w0 + 1;

    int hs[POOL], he[POOL], ws[POOL], we[POOL];
#pragma unroll
    for (int i = 0; i < POOL; i++) {
        hs[i] = h0 + (i * sh) / POOL;
        he[i] = h0 + ((i + 1) * sh + POOL - 1) / POOL;   // ceil
        ws[i] = w0 + (i * sw) / POOL;
        we[i] = w0 + ((i + 1) * sw + POOL - 1) / POOL;
    }

    size_t obase = (size_t)roi * KFC;
    for (int idx = threadIdx.x; idx < KFC; idx += blockDim.x) {
        int c  = idx / 49;
        int b  = idx - c * 49;
        int ph = b / POOL;
        int pw = b - ph * POOL;
        const float* base = fm + c * FHW;
        float m = -FLT_MAX;
        for (int h = hs[ph]; h < he[ph]; ++h) {
            const float* row = base + h * FW;
            for (int w = ws[pw]; w < we[pw]; ++w)
                m = fmaxf(m, row[w]);
        }
        __nv_bfloat16 hi = __float2bfloat16_rn(m);
        __nv_bfloat16 lo = __float2bfloat16_rn(m - __bfloat162float(hi));
        g_a_hi[obase + idx] = hi;
        g_a_lo[obase + idx] = lo;
    }
}

// ---------------------------------------------------------------------------
// Kernel 2: split-bf16 GEMM via mma.sync (HMMA), split-K, fused B convert.
// P[z, m, n] = sum_{k in split z} (Ah+Al)[m,k] * (Bh+Bl)[n,k]  (lo*lo dropped)
// CTA 128x128, 8 warps (2x4), warp tile 64x32, K-chunk 64, double-buffered.
// ---------------------------------------------------------------------------
__global__ __launch_bounds__(256) void fc_gemm_kernel(const float* __restrict__ W /*fc_w [NFC,KFC] fp32*/) {
    extern __shared__ char smem[];
    uint32_t sb = cvta_smem(smem);
    uint32_t tile0 = (sb + 1023u) & ~1023u;   // 1024-aligned base

    int tid  = threadIdx.x;
    int wid  = tid >> 5;
    int lane = tid & 31;
    int wm   = wid >> 2;        // 0..1 : warp row (64 m each)
    int wn   = wid & 3;         // 0..3 : warp col (32 n each)

    int n0 = blockIdx.x * 128;
    int m0 = blockIdx.y * 128;
    int z  = blockIdx.z;
    int nch = CHUNK_BASE + (z < CHUNK_REM ? 1 : 0);
    long kc0 = (long)z * CHUNK_BASE + (z < CHUNK_REM ? z : CHUNK_REM);

    const __nv_bfloat16* Ah = g_a_hi + (size_t)m0 * KFC;
    const __nv_bfloat16* Al = g_a_lo + (size_t)m0 * KFC;

    float acc[4][4][4];
#pragma unroll
    for (int i = 0; i < 4; i++)
#pragma unroll
        for (int j = 0; j < 4; j++)
#pragma unroll
            for (int q = 0; q < 4; q++) acc[i][j][q] = 0.f;

    // ---- preload chunk 0 into buffer 0 ----
    {
        uint32_t tb = tile0;
        size_t k0 = (size_t)kc0 * 64;
#pragma unroll
        for (int i = 0; i < 4; i++) {
            int u = tid + 256 * i;
            int row = u >> 3, slot = u & 7;
            size_t g = (size_t)row * KFC + k0 + slot * 8;
            uint32_t sw = sw128(row * 128 + slot * 16);
            cpasync16(tb + sw,          Ah + g);
            cpasync16(tb + TBYTES + sw, Al + g);
        }
#pragma unroll
        for (int i = 0; i < 4; i++) {
            int u = tid + 256 * i;
            int row = u >> 3, slot = u & 7;
            const float* src = W + (size_t)(n0 + row) * KFC + k0 + slot * 8;
            float f[8];
            *(float4*)(f + 0) = *(const float4*)(src + 0);
            *(float4*)(f + 4) = *(const float4*)(src + 4);
            bf16x8 hi, lo;
            split8(f, hi, lo);
            uint32_t sw = sw128(row * 128 + slot * 16);
            *(uint4*)(smem + (tb - sb) + 2 * TBYTES + sw) = *(const uint4*)&hi;
            *(uint4*)(smem + (tb - sb) + 3 * TBYTES + sw) = *(const uint4*)&lo;
        }
        cpasync_commit();
        cpasync_wait0();
        __syncthreads();
    }

    // lane-dependent ldmatrix address components
    int laneA_row = lane & 15;
    int laneA_kb  = ((lane >> 4) & 1) << 4;
    int laneB_row = lane & 7;
    int laneB_kb  = ((lane >> 3) & 1) << 4;

    for (int c = 0; c < nch; ++c) {
        int buf = c & 1;
        uint32_t tb  = tile0 + buf * BUFBYTES;
        uint32_t tbn = tile0 + (buf ^ 1) * BUFBYTES;

        // ---- prefetch next chunk: A via cp.async, B fp32 into registers ----
        float Bf[4][8];
        bool havenext = (c + 1 < nch);
        if (havenext) {
            size_t k0n = (size_t)(kc0 + c + 1) * 64;
#pragma unroll
            for (int i = 0; i < 4; i++) {
                int u = tid + 256 * i;
                int row = u >> 3, slot = u & 7;
                size_t g = (size_t)row * KFC + k0n + slot * 8;
                uint32_t sw = sw128(row * 128 + slot * 16);
                cpasync16(tbn + sw,          Ah + g);
                cpasync16(tbn + TBYTES + sw, Al + g);
            }
            cpasync_commit();
#pragma unroll
            for (int i = 0; i < 4; i++) {
                int u = tid + 256 * i;
                int row = u >> 3, slot = u & 7;
                const float* src = W + (size_t)(n0 + row) * KFC + k0n + slot * 8;
                *(float4*)(Bf[i] + 0) = *(const float4*)(src + 0);
                *(float4*)(Bf[i] + 4) = *(const float4*)(src + 4);
            }
        }

        // ---- compute on current buffer: 4 k-steps of 16 ----
        uint32_t tAh = tb, tAl = tb + TBYTES, tBh = tb + 2 * TBYTES, tBl = tb + 3 * TBYTES;
#pragma unroll
        for (int ks = 0; ks < 4; ks++) {
            uint32_t a_h[4][4], a_l[4][4], b_h[4][2], b_l[4][2];
#pragma unroll
            for (int i = 0; i < 4; i++) {
                uint32_t sw = sw128((wm * 64 + i * 16 + laneA_row) * 128 + ks * 32 + laneA_kb);
                ldm_x4(a_h[i], tAh + sw);
                ldm_x4(a_l[i], tAl + sw);
            }
#pragma unroll
            for (int j = 0; j < 4; j++) {
                uint32_t sw = sw128((wn * 32 + j * 8 + laneB_row) * 128 + ks * 32 + laneB_kb);
                ldm_x2(b_h[j], tBh + sw);
                ldm_x2(b_l[j], tBl + sw);
            }
#pragma unroll
            for (int i = 0; i < 4; i++)
#pragma unroll
                for (int j = 0; j < 4; j++) {
                    mma_bf16(acc[i][j], a_h[i], b_h[j]);   // hi*hi
                    mma_bf16(acc[i][j], a_h[i], b_l[j]);   // hi*lo
                    mma_bf16(acc[i][j], a_l[i], b_h[j]);   // lo*hi
                }
        }

        // ---- store prefetched B into next buffer, wait cp.async, sync ----
        if (havenext) {
#pragma unroll
            for (int i = 0; i < 4; i++) {
                int u = tid + 256 * i;
                int row = u >> 3, slot = u & 7;
                bf16x8 hi, lo;
                split8(Bf[i], hi, lo);
                uint32_t sw = sw128(row * 128 + slot * 16);
                *(uint4*)(smem + (tbn - sb) + 2 * TBYTES + sw) = *(const uint4*)&hi;
                *(uint4*)(smem + (tbn - sb) + 3 * TBYTES + sw) = *(const uint4*)&lo;
            }
            cpasync_wait0();
        }
        __syncthreads();
    }

    // ---- epilogue: c-frag -> g_partial[z][m][n] ----
    int g   = lane >> 2;          // 0..7
    int tig = lane & 3;           // 0..3
#pragma unroll
    for (int i = 0; i < 4; i++) {
#pragma unroll
        for (int j = 0; j < 4; j++) {
            int m = m0 + wm * 64 + i * 16 + g;
            int n = n0 + wn * 32 + j * 8 + tig * 2;
            float* P = g_partial + ((size_t)z * NROI + m) * NFC + n;
            *(float2*)P             = make_float2(acc[i][j][0], acc[i][j][1]);
            *(float2*)(P + 8 * NFC) = make_float2(acc[i][j][2], acc[i][j][3]);
        }
    }
}

// ---------------------------------------------------------------------------
// Kernel 3: split-K reduce + bias + ReLU -> r[256,1024]
// ---------------------------------------------------------------------------
__global__ __launch_bounds__(256) void fc_reduce_kernel(const float* __restrict__ fcb) {
    int i = blockIdx.x * blockDim.x + threadIdx.x;   // < NROI*NFC
    float s = 0.f;
#pragma unroll
    for (int z = 0; z < SPLITK; z++)
        s += g_partial[(size_t)z * NROI * NFC + i];
    s += fcb[i & (NFC - 1)];
    g_r[i] = fmaxf(s, 0.f);
}

// ---------------------------------------------------------------------------
// Kernel 4: heads. cls 21 dots, argmax (first-max), 4 reg dots for best class.
// Output: [256*21] cls, then [256*4] reg.
// ---------------------------------------------------------------------------
__global__ __launch_bounds__(128) void heads_kernel(const float* __restrict__ cls_w,
                                                    const float* __restrict__ cls_b,
                                                    const float* __restrict__ reg_w,
                                                    const float* __restrict__ reg_b,
                                                    float* __restrict__ out) {
    __shared__ float rs[NFC];
    __shared__ float scls[NCLS];
    __shared__ int sbest;

    int roi = blockIdx.x;
    int tid = threadIdx.x;

    for (int k = tid; k < NFC; k += 128)
        rs[k] = g_r[(size_t)roi * NFC + k];
    __syncthreads();

    if (tid < NCLS) {
        const float* w = cls_w + (size_t)tid * NFC;
        float a0 = 0.f, a1 = 0.f, a2 = 0.f, a3 = 0.f;
#pragma unroll 4
        for (int k = 0; k < NFC; k += 4) {
            a0 += rs[k + 0] * w[k + 0];
            a1 += rs[k + 1] * w[k + 1];
            a2 += rs[k + 2] * w[k + 2];
            a3 += rs[k + 3] * w[k + 3];
        }
        float acc = (a0 + a1) + (a2 + a3) + cls_b[tid];
        scls[tid] = acc;
        out[roi * NCLS + tid] = acc;
    }
    __syncthreads();

    if (tid == 0) {
        int best = 0;
        float bv = scls[0];
        for (int j = 1; j < NCLS; j++)
            if (scls[j] > bv) { bv = scls[j]; best = j; }
        sbest = best;
    }
    __syncthreads();

    int d = tid >> 5;
    int lane = tid & 31;
    const float* w = reg_w + (size_t)(sbest * 4 + d) * NFC;
    float acc = 0.f;
    for (int k = lane; k < NFC; k += 32)
        acc += rs[k] * w[k];
#pragma unroll
    for (int o = 16; o > 0; o >>= 1)
        acc += __shfl_down_sync(0xffffffffu, acc, o);
    if (lane == 0)
        out[NROI * NCLS + roi * 4 + d] = acc + reg_b[sbest * 4 + d];
}

// ---------------------------------------------------------------------------
extern "C" void kernel_launch(void* const* d_in, const int* in_sizes, int n_in,
                              void* d_out, int out_size) {
    const float* fm    = (const float*)d_in[0];
    const int*   prop  = (const int*)  d_in[1];
    const float* fc_w  = (const float*)d_in[2];
    const float* fc_b  = (const float*)d_in[3];
    const float* cls_w = (const float*)d_in[4];
    const float* cls_b = (const float*)d_in[5];
    const float* reg_w = (const float*)d_in[6];
    const float* reg_b = (const float*)d_in[7];
    float* out = (float*)d_out;

    cudaFuncSetAttribute(fc_gemm_kernel,
                         cudaFuncAttributeMaxDynamicSharedMemorySize, SMEM_DYN);

    roi_pool_kernel<<<NROI, 512>>>(fm, prop);
    fc_gemm_kernel<<<dim3(NFC / 128, NROI / 128, SPLITK), 256, SMEM_DYN>>>(fc_w);
    fc_reduce_kernel<<<(NROI * NFC) / 256, 256>>>(fc_b);
    heads_kernel<<<NROI, 128>>>(cls_w, cls_b, reg_w, reg_b, out);
}